// round 5
// baseline (speedup 1.0000x reference)
#include <cuda_runtime.h>
#include <cuda_bf16.h>
#include <cstdint>

// Fixed shapes: B=2, H=8, N=256, D=64.  One CTA (512 thr, 16 warps) per query.
// Warp w owns k-rows [16w, 16w+16).
#define NQ 256
#define DD 64
#define NPANEL 4

// SMEM rows padded to 144B: every ldmatrix phase hits 8 distinct bank groups.
#define RS 144
static constexpr uint32_t OFF_K2H = 0;                       // [256 k][64 d] bf16 hi
static constexpr uint32_t OFF_K2L = 36864;
static constexpr uint32_t OFF_QHH = 73728;                   // [256 j][64 d] bf16 hi (q*k1*log2e)
static constexpr uint32_t OFF_QHL = 110592;
static constexpr uint32_t OFF_V1H = 147456;                  // [64 j][64 d] bf16 hi (panel)
static constexpr uint32_t OFF_V1L = 156672;
static constexpr uint32_t OFF_SRED = 165888;                 // [16 warps][64 d] fp32
static constexpr uint32_t OFF_SLP  = 169984;                 // [16] fp32 lsum partials
static constexpr uint32_t SMEM_BYTES = 170048;

// ---------------- PTX helpers ----------------------------------------------
__device__ __forceinline__ uint32_t smem_u32(const void* p) {
    uint32_t a;
    asm("{ .reg .u64 t; cvta.to.shared.u64 t, %1; cvt.u32.u64 %0, t; }" : "=r"(a) : "l"(p));
    return a;
}
__device__ __forceinline__ float ex2f(float x) {
    float y; asm("ex2.approx.ftz.f32 %0, %1;" : "=f"(y) : "f"(x)); return y;
}
__device__ __forceinline__ void ldsm_x4(uint32_t* r, uint32_t addr) {
    asm volatile("ldmatrix.sync.aligned.m8n8.x4.shared.b16 {%0,%1,%2,%3}, [%4];"
                 : "=r"(r[0]), "=r"(r[1]), "=r"(r[2]), "=r"(r[3]) : "r"(addr));
}
__device__ __forceinline__ void ldsm_x4_t(uint32_t* r, uint32_t addr) {
    asm volatile("ldmatrix.sync.aligned.m8n8.x4.trans.shared.b16 {%0,%1,%2,%3}, [%4];"
                 : "=r"(r[0]), "=r"(r[1]), "=r"(r[2]), "=r"(r[3]) : "r"(addr));
}
__device__ __forceinline__ void mma16816(float* c, const uint32_t* a, uint32_t b0, uint32_t b1) {
    asm volatile("mma.sync.aligned.m16n8k16.row.col.f32.bf16.bf16.f32 "
                 "{%0,%1,%2,%3}, {%4,%5,%6,%7}, {%8,%9}, {%0,%1,%2,%3};"
                 : "+f"(c[0]), "+f"(c[1]), "+f"(c[2]), "+f"(c[3])
                 : "r"(a[0]), "r"(a[1]), "r"(a[2]), "r"(a[3]), "r"(b0), "r"(b1));
}
// split (x,y) into bf16 hi pair and residual-lo pair (packed b16x2, x low half)
__device__ __forceinline__ void split2(float x, float y, uint32_t& h, uint32_t& l) {
    __nv_bfloat162 h2 = __floats2bfloat162_rn(x, y);
    __nv_bfloat162 l2 = __floats2bfloat162_rn(x - __low2float(h2), y - __high2float(h2));
    h = *(uint32_t*)&h2; l = *(uint32_t*)&l2;
}

// ---------------- Kernel ----------------------------------------------------
__global__ __launch_bounds__(512, 1)
void trisimp_mma_kernel(const float* __restrict__ q,  const float* __restrict__ k1,
                        const float* __restrict__ v1, const float* __restrict__ k2,
                        const float* __restrict__ v2, float* __restrict__ out)
{
    extern __shared__ char smem[];
    const uint32_t sb = smem_u32(smem);
    const int tid = threadIdx.x, w = tid >> 5, lid = tid & 31;
    const int g = lid >> 2, t = lid & 3;

    const int bhq = blockIdx.x, qi = bhq & 255, bh = bhq >> 8;
    const size_t base = (size_t)bh * NQ * DD;
    const float* Qrow = q  + base + (size_t)qi * DD;
    const float* K1g  = k1 + base;
    const float* V1g  = v1 + base;
    const float* K2g  = k2 + base;
    const float* V2g  = v2 + base;

    // ---- stage K2 hi/lo and Qh hi/lo: [row][64 d], 144B row stride ----
    {
        const float2* K2g2 = (const float2*)K2g;
        const float2* K1g2 = (const float2*)K1g;
        const int dp = tid & 31;                     // constant per thread (512 % 32 == 0)
        const float2 qp = ((const float2*)Qrow)[dp];
        const float qx = qp.x * 1.4426950408889634f;
        const float qy = qp.y * 1.4426950408889634f;
        for (int e2 = tid; e2 < NQ * 32; e2 += 512) {
            const int r = e2 >> 5;
            const uint32_t off = (uint32_t)r * RS + (uint32_t)dp * 4;
            {
                const float2 x = K2g2[e2];
                uint32_t h, l; split2(x.x, x.y, h, l);
                *(uint32_t*)(smem + OFF_K2H + off) = h;
                *(uint32_t*)(smem + OFF_K2L + off) = l;
            }
            {
                const float2 x = K1g2[e2];
                uint32_t h, l; split2(qx * x.x, qy * x.y, h, l);
                *(uint32_t*)(smem + OFF_QHH + off) = h;
                *(uint32_t*)(smem + OFF_QHL + off) = l;
            }
        }
    }

    // ldmatrix address templates
    const uint32_t lm_a = (uint32_t)(lid & 15) * RS + (uint32_t)(lid >> 4) * 16;          // A / trans-B
    const uint32_t lm_b = (uint32_t)((lid >> 4) * 8 + (lid & 7)) * RS + (uint32_t)((lid >> 3) & 1) * 16; // non-trans B

    float o[8][4];                                   // D2 accum: [d-tile][frag], 16 k-rows
    #pragma unroll
    for (int nt = 0; nt < 8; ++nt)
        #pragma unroll
        for (int r = 0; r < 4; ++r) o[nt][r] = 0.f;
    float lsum = 0.f;

    #pragma unroll 1
    for (int p = 0; p < NPANEL; ++p) {
        __syncthreads();                             // V1 buf free (+ staging done, p==0)
        // ---- stage V1 panel hi/lo [64 j][64 d] ----
        {
            const float2* V1p2 = (const float2*)(V1g + (size_t)p * 64 * DD);
            const int dp = tid & 31;
            for (int e2 = tid; e2 < 64 * 32; e2 += 512) {
                const int r = e2 >> 5;
                const float2 x = V1p2[e2];
                uint32_t h, l; split2(x.x, x.y, h, l);
                const uint32_t off = (uint32_t)r * RS + (uint32_t)dp * 4;
                *(uint32_t*)(smem + OFF_V1H + off) = h;
                *(uint32_t*)(smem + OFF_V1L + off) = l;
            }
        }
        __syncthreads();                             // V1 ready

        // ---- GEMM1: S[k, j] = sum_d K2[k,d] * Qh[j,d]  (hi/lo 3-product) ----
        float s[8][4];
        #pragma unroll
        for (int nt = 0; nt < 8; ++nt)
            #pragma unroll
            for (int r = 0; r < 4; ++r) s[nt][r] = 0.f;

        #pragma unroll
        for (int kc = 0; kc < 4; ++kc) {             // d-chunks of 16
            uint32_t aH[4], aL[4];
            {
                const uint32_t rowb = (uint32_t)(16 * w) * RS + (uint32_t)kc * 32;
                ldsm_x4(aH, sb + OFF_K2H + rowb + lm_a);
                ldsm_x4(aL, sb + OFF_K2L + rowb + lm_a);
            }
            #pragma unroll
            for (int cp = 0; cp < 4; ++cp) {         // j-tile pairs
                uint32_t bH[4], bL[4];
                const uint32_t rowb = (uint32_t)(64 * p + 16 * cp) * RS + (uint32_t)kc * 32;
                ldsm_x4(bH, sb + OFF_QHH + rowb + lm_b);   // {b0_n0,b1_n0,b0_n1,b1_n1}
                ldsm_x4(bL, sb + OFF_QHL + rowb + lm_b);
                // interleave products across the two accumulators (no back-to-back RAW)
                mma16816(s[2*cp],   aH, bH[0], bH[1]);
                mma16816(s[2*cp+1], aH, bH[2], bH[3]);
                mma16816(s[2*cp],   aH, bL[0], bL[1]);
                mma16816(s[2*cp+1], aH, bL[2], bL[3]);
                mma16816(s[2*cp],   aL, bH[0], bH[1]);
                mma16816(s[2*cp+1], aL, bH[2], bH[3]);
            }
        }

        // ---- per j16-chunk: exp2, pack P hi/lo as A-frags, GEMM2 ----
        #pragma unroll
        for (int c = 0; c < 4; ++c) {
            uint32_t paH[4], paL[4];
            #pragma unroll
            for (int h = 0; h < 2; ++h) {
                float* cc = s[2 * c + h];
                const float p0 = ex2f(cc[0]), p1 = ex2f(cc[1]);
                const float p2 = ex2f(cc[2]), p3 = ex2f(cc[3]);
                lsum += (p0 + p1) + (p2 + p3);
                split2(p0, p1, paH[2*h],   paL[2*h]);     // rows g   (a0/a2)
                split2(p2, p3, paH[2*h+1], paL[2*h+1]);   // rows g+8 (a1/a3)
            }
            #pragma unroll
            for (int ntp = 0; ntp < 4; ++ntp) {      // d-tile pairs
                uint32_t vH[4], vL[4];
                const uint32_t rowb = (uint32_t)(16 * c) * RS + (uint32_t)ntp * 32;
                ldsm_x4_t(vH, sb + OFF_V1H + rowb + lm_a);   // {b0_d0,b1_d0,b0_d1,b1_d1}
                ldsm_x4_t(vL, sb + OFF_V1L + rowb + lm_a);
                mma16816(o[2*ntp],   paH, vH[0], vH[1]);
                mma16816(o[2*ntp+1], paH, vH[2], vH[3]);
                mma16816(o[2*ntp],   paH, vL[0], vL[1]);
                mma16816(o[2*ntp+1], paH, vL[2], vL[3]);
                mma16816(o[2*ntp],   paL, vH[0], vH[1]);
                mma16816(o[2*ntp+1], paL, vH[2], vH[3]);
            }
        }
    }

    // ---- epilogue: out[d] = sum_k D2[k,d] * v2[k,d] / sum(exp) ----
    float* sRed = (float*)(smem + OFF_SRED);
    float* sLp  = (float*)(smem + OFF_SLP);
    {
        const int k0 = 16 * w + g;
        #pragma unroll
        for (int nt = 0; nt < 8; ++nt) {
            const int d0 = 8 * nt + 2 * t;
            const float2 vA = *(const float2*)(V2g + (size_t)(k0)     * DD + d0);
            const float2 vB = *(const float2*)(V2g + (size_t)(k0 + 8) * DD + d0);
            float r0 = o[nt][0] * vA.x + o[nt][2] * vB.x;
            float r1 = o[nt][1] * vA.y + o[nt][3] * vB.y;
            #pragma unroll
            for (int m = 4; m <= 16; m <<= 1) {      // reduce over g (rows)
                r0 += __shfl_xor_sync(0xffffffffu, r0, m);
                r1 += __shfl_xor_sync(0xffffffffu, r1, m);
            }
            if (g == 0) *(float2*)(sRed + w * 64 + d0) = make_float2(r0, r1);
        }
        #pragma unroll
        for (int m = 16; m; m >>= 1)
            lsum += __shfl_xor_sync(0xffffffffu, lsum, m);
        if (lid == 0) sLp[w] = lsum;
    }
    __syncthreads();

    if (tid < 64) {
        float ssum = 0.f;
        #pragma unroll
        for (int ww = 0; ww < 16; ++ww) ssum += sRed[ww * 64 + tid];
        float l = 0.f;
        #pragma unroll
        for (int ww = 0; ww < 16; ++ww) l += sLp[ww];
        out[base + (size_t)qi * DD + tid] = ssum / l;
    }
}

extern "C" void kernel_launch(void* const* d_in, const int* in_sizes, int n_in,
                              void* d_out, int out_size)
{
    const float* q  = (const float*)d_in[0];
    const float* k1 = (const float*)d_in[1];
    const float* v1 = (const float*)d_in[2];
    const float* k2 = (const float*)d_in[3];
    const float* v2 = (const float*)d_in[4];
    float* out = (float*)d_out;

    (void)cudaFuncSetAttribute(trisimp_mma_kernel,
                               cudaFuncAttributeMaxDynamicSharedMemorySize, SMEM_BYTES);
    trisimp_mma_kernel<<<2 * 8 * NQ, 512, SMEM_BYTES>>>(q, k1, v1, k2, v2, out);
}